// round 5
// baseline (speedup 1.0000x reference)
#include <cuda_runtime.h>
#include <cuda_bf16.h>

// ---------------------------------------------------------------------------
// DisableGateLSTM: B=64, T=512, E=256, H=512, C=4
// Phase 1: pre[t][row][b] = bias[row] + sum_k emb[ids[b][t]][k] * W_g[r][512+k]
//          (rows 0..2047 ordered f,i,o,c; 512 rows per gate)
// Phase 2: persistent-kernel recurrence over t (grid barrier per step)
// Phase 3: logits = (max_t h) @ fc_w^T + fc_b
// ---------------------------------------------------------------------------

#define T_SEQ 512
#define NB    64
#define NE    256
#define NH    512
#define NG    2048
#define RECUR_CTAS 128

typedef unsigned long long u64;

static __device__ float g_pre[(size_t)T_SEQ * NG * NB];   // [t][row][b]
static __device__ float g_h[2][NH * NB];                  // ping-pong h, [j][b]
static __device__ float g_hmax[NH * NB];                  // [j][b]
static __device__ int   g_count;                          // grid barrier
static __device__ int   g_sense;

// ---------------- f32x2 helpers ----------------
static __device__ __forceinline__ u64 fma2(u64 a, u64 b, u64 c) {
    u64 d;
    asm("fma.rn.f32x2 %0, %1, %2, %3;" : "=l"(d) : "l"(a), "l"(b), "l"(c));
    return d;
}
static __device__ __forceinline__ float2 upk2(u64 a) {
    float2 f;
    asm("mov.b64 {%0, %1}, %2;" : "=f"(f.x), "=f"(f.y) : "l"(a));
    return f;
}

static __device__ __forceinline__ float sigf(float x) {
    return 1.f / (1.f + __expf(-x));
}
static __device__ __forceinline__ float tanh_fast(float x) {
    return 2.f / (1.f + __expf(-2.f * x)) - 1.f;
}

// cp.async.cg: L2-only path => coherent with other SMs' global stores
static __device__ __forceinline__ void cpa16(void* dst, const void* src) {
    unsigned s = (unsigned)__cvta_generic_to_shared(dst);
    asm volatile("cp.async.cg.shared.global [%0], [%1], 16;" :: "r"(s), "l"(src) : "memory");
}

// =====================================================================
// Phase 1: pre-GEMM.  grid = (16 j-tiles, 256 m-tiles), 256 threads.
// C[row 2048][m 32768], m = t*64+b, K = 256.  Tile 128x128, thread 8x8.
// As stored DUPLICATED (w,w) so inner loop is pure fma.rn.f32x2.
// =====================================================================
__global__ void __launch_bounds__(256, 2) pre_gemm(
    const int* __restrict__ ids, const float* __restrict__ emb,
    const float* __restrict__ Wf, const float* __restrict__ bf,
    const float* __restrict__ Wi, const float* __restrict__ bi,
    const float* __restrict__ Wo, const float* __restrict__ bo,
    const float* __restrict__ Wc, const float* __restrict__ bc)
{
    __shared__ float As[2][16][256];   // [kk][2*j] duplicated pairs
    __shared__ float Bs[2][16][128];   // [kk][m]

    const int t  = threadIdx.x;
    const int gx = blockIdx.x;           // 0..15: gate = gx>>2
    const int m0 = blockIdx.y * 128;
    const int tx = t & 15, ty = t >> 4;

    const float* W    = (gx < 4) ? Wf : (gx < 8) ? Wi : (gx < 12) ? Wo : Wc;
    const float* bias = (gx < 4) ? bf : (gx < 8) ? bi : (gx < 12) ? bo : bc;
    const int jg0 = (gx & 3) * 128;      // row base within gate

    // fixed per-thread load slots: v0 = t, v1 = t+256
    const int jA0 = t >> 2;              // 0..63
    const int jA1 = jA0 + 64;            // 64..127
    const int qA  = t & 3;
    const int ml0 = t >> 2;              // Bs m-local slots
    const int ml1 = ml0 + 64;
    const int mg0 = m0 + ml0, mg1 = m0 + ml1;
    const int id0 = ids[(mg0 & 63) * T_SEQ + (mg0 >> 6)];
    const int id1 = ids[(mg1 & 63) * T_SEQ + (mg1 >> 6)];

    u64 acc[8][4];
#pragma unroll
    for (int jj = 0; jj < 8; ++jj)
#pragma unroll
        for (int s = 0; s < 4; ++s) acc[jj][s] = 0ull;

    float4 a0, a1, b0v, b1v;

    // prologue: chunk 0
    {
        const int k0 = 0;
        a0  = *(const float4*)&W[(size_t)(jg0 + jA0) * 768 + 512 + k0 + qA * 4];
        a1  = *(const float4*)&W[(size_t)(jg0 + jA1) * 768 + 512 + k0 + qA * 4];
        b0v = *(const float4*)&emb[(size_t)id0 * NE + k0 + qA * 4];
        b1v = *(const float4*)&emb[(size_t)id1 * NE + k0 + qA * 4];
    }
    {
        const int st = 0;
        As[st][qA*4+0][2*jA0] = a0.x; As[st][qA*4+0][2*jA0+1] = a0.x;
        As[st][qA*4+1][2*jA0] = a0.y; As[st][qA*4+1][2*jA0+1] = a0.y;
        As[st][qA*4+2][2*jA0] = a0.z; As[st][qA*4+2][2*jA0+1] = a0.z;
        As[st][qA*4+3][2*jA0] = a0.w; As[st][qA*4+3][2*jA0+1] = a0.w;
        As[st][qA*4+0][2*jA1] = a1.x; As[st][qA*4+0][2*jA1+1] = a1.x;
        As[st][qA*4+1][2*jA1] = a1.y; As[st][qA*4+1][2*jA1+1] = a1.y;
        As[st][qA*4+2][2*jA1] = a1.z; As[st][qA*4+2][2*jA1+1] = a1.z;
        As[st][qA*4+3][2*jA1] = a1.w; As[st][qA*4+3][2*jA1+1] = a1.w;
        Bs[st][qA*4+0][ml0] = b0v.x; Bs[st][qA*4+1][ml0] = b0v.y;
        Bs[st][qA*4+2][ml0] = b0v.z; Bs[st][qA*4+3][ml0] = b0v.w;
        Bs[st][qA*4+0][ml1] = b1v.x; Bs[st][qA*4+1][ml1] = b1v.y;
        Bs[st][qA*4+2][ml1] = b1v.z; Bs[st][qA*4+3][ml1] = b1v.w;
    }
    __syncthreads();

    int st = 0;
    for (int c = 0; c < 16; ++c) {
        if (c < 15) {
            const int k0 = (c + 1) * 16;
            a0  = *(const float4*)&W[(size_t)(jg0 + jA0) * 768 + 512 + k0 + qA * 4];
            a1  = *(const float4*)&W[(size_t)(jg0 + jA1) * 768 + 512 + k0 + qA * 4];
            b0v = *(const float4*)&emb[(size_t)id0 * NE + k0 + qA * 4];
            b1v = *(const float4*)&emb[(size_t)id1 * NE + k0 + qA * 4];
        }
        // compute current stage
#pragma unroll 4
        for (int kk = 0; kk < 16; ++kk) {
            ulonglong2 A01 = *(const ulonglong2*)&As[st][kk][ty * 16 + 0];
            ulonglong2 A23 = *(const ulonglong2*)&As[st][kk][ty * 16 + 4];
            ulonglong2 A45 = *(const ulonglong2*)&As[st][kk][ty * 16 + 8];
            ulonglong2 A67 = *(const ulonglong2*)&As[st][kk][ty * 16 + 12];
            u64 af[8] = {A01.x, A01.y, A23.x, A23.y, A45.x, A45.y, A67.x, A67.y};
            u64 bfr[4];
#pragma unroll
            for (int s = 0; s < 4; ++s)
                bfr[s] = *(const u64*)&Bs[st][kk][tx * 2 + s * 32];
#pragma unroll
            for (int jj = 0; jj < 8; ++jj)
#pragma unroll
                for (int s = 0; s < 4; ++s)
                    acc[jj][s] = fma2(bfr[s], af[jj], acc[jj][s]);
        }
        if (c < 15) {
            const int sn = st ^ 1;
            As[sn][qA*4+0][2*jA0] = a0.x; As[sn][qA*4+0][2*jA0+1] = a0.x;
            As[sn][qA*4+1][2*jA0] = a0.y; As[sn][qA*4+1][2*jA0+1] = a0.y;
            As[sn][qA*4+2][2*jA0] = a0.z; As[sn][qA*4+2][2*jA0+1] = a0.z;
            As[sn][qA*4+3][2*jA0] = a0.w; As[sn][qA*4+3][2*jA0+1] = a0.w;
            As[sn][qA*4+0][2*jA1] = a1.x; As[sn][qA*4+0][2*jA1+1] = a1.x;
            As[sn][qA*4+1][2*jA1] = a1.y; As[sn][qA*4+1][2*jA1+1] = a1.y;
            As[sn][qA*4+2][2*jA1] = a1.z; As[sn][qA*4+2][2*jA1+1] = a1.z;
            As[sn][qA*4+3][2*jA1] = a1.w; As[sn][qA*4+3][2*jA1+1] = a1.w;
            Bs[sn][qA*4+0][ml0] = b0v.x; Bs[sn][qA*4+1][ml0] = b0v.y;
            Bs[sn][qA*4+2][ml0] = b0v.z; Bs[sn][qA*4+3][ml0] = b0v.w;
            Bs[sn][qA*4+0][ml1] = b1v.x; Bs[sn][qA*4+1][ml1] = b1v.y;
            Bs[sn][qA*4+2][ml1] = b1v.z; Bs[sn][qA*4+3][ml1] = b1v.w;
        }
        __syncthreads();
        st ^= 1;
    }

    // epilogue
#pragma unroll
    for (int jj = 0; jj < 8; ++jj) {
        const int row = gx * 128 + ty * 8 + jj;
        const float bv = bias[(gx & 3) * 128 + ty * 8 + jj];
#pragma unroll
        for (int s = 0; s < 4; ++s) {
            float2 v = upk2(acc[jj][s]);
            v.x += bv; v.y += bv;
            const int m = m0 + tx * 2 + s * 32;
            const size_t off = ((size_t)(m >> 6) * NG + row) * NB + (m & 63);
            *(float2*)&g_pre[off] = v;
        }
    }
}

// =====================================================================
// Phase 2: persistent recurrence.  128 CTAs x 256 threads.
// CTA owns h rows [4*bid, 4*bid+4) across all 4 gates.
// Thread: half = t>>7 (k-split), jl = (t&127)>>5, b-pair b0 = 2*(t&31).
// =====================================================================
static __device__ __forceinline__ void grid_barrier(int* sense) {
    __threadfence();
    __syncthreads();
    if (threadIdx.x == 0) {
        const int s = *sense ^ 1;
        *sense = s;
        if (atomicAdd(&g_count, 1) == RECUR_CTAS - 1) {
            *(volatile int*)&g_count = 0;
            __threadfence();
            *(volatile int*)&g_sense = s;
        } else {
            while (*(volatile int*)&g_sense != s) { }
        }
        __threadfence();
    }
    __syncthreads();
}

__global__ void __launch_bounds__(256) lstm_recur(
    const float* __restrict__ Wf, const float* __restrict__ Wi,
    const float* __restrict__ Wo, const float* __restrict__ Wc)
{
    extern __shared__ float smem[];
    float* hs = smem;                       // 512*64 floats (128 KB)
    float* Wd = smem + NH * NB;             // 16*1024 floats dup (64 KB)
    u64*  red = (u64*)(Wd + 16 * 1024);     // 512 u64 (4 KB)

    const int t    = threadIdx.x;
    const int bid  = blockIdx.x;
    const int half = t >> 7;
    const int uu   = t & 127;
    const int jl   = uu >> 5;
    const int b0   = (uu & 31) * 2;
    const int hrow = bid * 4 + jl;

    // load W h-part (cols 0..511), duplicated pairs
    {
        const float* Ws[4] = {Wf, Wi, Wo, Wc};
#pragma unroll
        for (int i = 0; i < 8; ++i) {
            const int w  = t + 256 * i;      // float4 slot, 0..2047
            const int r  = w >> 7;           // 0..15 = g*4 + jlocal
            const int g  = r >> 2, j2 = r & 3;
            const int kq = (w & 127) * 4;
            float4 v = *(const float4*)&Ws[g][(size_t)(bid * 4 + j2) * 768 + kq];
            float* d = Wd + r * 1024 + 2 * kq;
            d[0] = v.x; d[1] = v.x; d[2] = v.y; d[3] = v.y;
            d[4] = v.z; d[5] = v.z; d[6] = v.w; d[7] = v.w;
        }
    }
    // zero this CTA's slice of h[0]
    g_h[0][(bid * 4 + (t >> 6)) * 64 + (t & 63)] = 0.f;

    int sense = 0;
    grid_barrier(&sense);                    // barrier #1

    float cva = 0.f, cvb = 0.f;
    float hma = -1e30f, hmb = -1e30f;

    for (int step = 0; step < T_SEQ; ++step) {
        const float* hin = g_h[step & 1];
        // issue 4 cp.async groups; group i covers k [i*64,i*64+64) U [256+i*64,...)
        {
            const float4* src = (const float4*)hin;
            float4* dst = (float4*)hs;
#pragma unroll
            for (int gi = 0; gi < 4; ++gi) {
#pragma unroll
                for (int q = 0; q < 4; ++q) {
                    const int idx = gi * 1024 + q * 256 + t;
                    cpa16(dst + idx, src + idx);
                    cpa16(dst + 4096 + idx, src + 4096 + idx);
                }
                asm volatile("cp.async.commit_group;" ::: "memory");
            }
        }
        // prefetch pre (needed only by half 0 at combine time)
        float2 pv[4];
        if (half == 0) {
#pragma unroll
            for (int g = 0; g < 4; ++g)
                pv[g] = *(const float2*)&g_pre[((size_t)step * NG + g * NH + hrow) * NB + b0];
        }

        u64 acc[4] = {0ull, 0ull, 0ull, 0ull};
        const int kb0 = half * 256;
#pragma unroll
        for (int sub = 0; sub < 4; ++sub) {
            if      (sub == 0) asm volatile("cp.async.wait_group 3;" ::: "memory");
            else if (sub == 1) asm volatile("cp.async.wait_group 2;" ::: "memory");
            else if (sub == 2) asm volatile("cp.async.wait_group 1;" ::: "memory");
            else               asm volatile("cp.async.wait_group 0;" ::: "memory");
            __syncthreads();
            const int kb = kb0 + sub * 64;
#pragma unroll 2
            for (int kk = 0; kk < 64; kk += 4) {
                const int k = kb + kk;
                u64 h0 = *(const u64*)&hs[(k + 0) * 64 + b0];
                u64 h1 = *(const u64*)&hs[(k + 1) * 64 + b0];
                u64 h2 = *(const u64*)&hs[(k + 2) * 64 + b0];
                u64 h3 = *(const u64*)&hs[(k + 3) * 64 + b0];
#pragma unroll
                for (int g = 0; g < 4; ++g) {
                    const float* wp = Wd + (g * 4 + jl) * 1024 + 2 * k;
                    ulonglong2 wa = *(const ulonglong2*)wp;
                    ulonglong2 wb = *(const ulonglong2*)(wp + 4);
                    acc[g] = fma2(h0, wa.x, acc[g]);
                    acc[g] = fma2(h1, wa.y, acc[g]);
                    acc[g] = fma2(h2, wb.x, acc[g]);
                    acc[g] = fma2(h3, wb.y, acc[g]);
                }
            }
        }

        // combine halves + pointwise LSTM cell
        if (half == 1) {
#pragma unroll
            for (int g = 0; g < 4; ++g) red[uu * 4 + g] = acc[g];
        }
        __syncthreads();
        if (half == 0) {
            float2 gf = upk2(acc[0]), gi2 = upk2(acc[1]);
            float2 go = upk2(acc[2]), gc = upk2(acc[3]);
            float2 rf = upk2(red[uu * 4 + 0]), ri = upk2(red[uu * 4 + 1]);
            float2 ro = upk2(red[uu * 4 + 2]), rc = upk2(red[uu * 4 + 3]);
            const float fa = sigf(gf.x + rf.x + pv[0].x);
            const float fb = sigf(gf.y + rf.y + pv[0].y);
            const float ia = sigf(gi2.x + ri.x + pv[1].x);
            const float ib = sigf(gi2.y + ri.y + pv[1].y);
            const float oa = sigf(go.x + ro.x + pv[2].x);
            const float ob = sigf(go.y + ro.y + pv[2].y);
            const float ga = tanh_fast(gc.x + rc.x + pv[3].x);
            const float gb = tanh_fast(gc.y + rc.y + pv[3].y);
            cva = fa * cva + ia * ga;
            cvb = fb * cvb + ib * gb;
            const float ha = oa * tanh_fast(cva);
            const float hb = ob * tanh_fast(cvb);
            hma = fmaxf(hma, ha);
            hmb = fmaxf(hmb, hb);
            *(float2*)&g_h[(step + 1) & 1][hrow * 64 + b0] = make_float2(ha, hb);
        }
        grid_barrier(&sense);                // barriers #2..#513
    }

    if (half == 0)
        *(float2*)&g_hmax[hrow * 64 + b0] = make_float2(hma, hmb);
    grid_barrier(&sense);                    // barrier #514 (even count per launch)
}

// =====================================================================
// Phase 3: logits[b][c] = fc_b[c] + sum_j hmax[j][b] * fc_w[c][j]
// =====================================================================
__global__ void fc_kernel(const float* __restrict__ fcw,
                          const float* __restrict__ fcb,
                          float* __restrict__ out)
{
    const int t = threadIdx.x;
    const int b = t & 63, c = t >> 6;
    float acc = 0.f;
#pragma unroll 8
    for (int j = 0; j < NH; ++j)
        acc += g_hmax[j * 64 + b] * fcw[c * NH + j];
    out[b * 4 + c] = acc + fcb[c];
}

// =====================================================================
extern "C" void kernel_launch(void* const* d_in, const int* in_sizes, int n_in,
                              void* d_out, int out_size)
{
    (void)in_sizes; (void)n_in; (void)out_size;
    const int*   ids = (const int*)  d_in[0];
    const float* emb = (const float*)d_in[1];
    const float* Wf  = (const float*)d_in[2];
    const float* bf  = (const float*)d_in[3];
    const float* Wi  = (const float*)d_in[4];
    const float* bi  = (const float*)d_in[5];
    const float* Wo  = (const float*)d_in[6];
    const float* bo  = (const float*)d_in[7];
    const float* Wc  = (const float*)d_in[8];
    const float* bc  = (const float*)d_in[9];
    const float* fcw = (const float*)d_in[10];
    const float* fcb = (const float*)d_in[11];
    float* out = (float*)d_out;

    const int recur_smem = (NH * NB + 16 * 1024) * 4 + 512 * 8;  // 200704 B
    cudaFuncSetAttribute(lstm_recur, cudaFuncAttributeMaxDynamicSharedMemorySize, recur_smem);

    pre_gemm<<<dim3(16, 256), 256>>>(ids, emb, Wf, bf, Wi, bi, Wo, bo, Wc, bc);
    lstm_recur<<<RECUR_CTAS, 256, recur_smem>>>(Wf, Wi, Wo, Wc);
    fc_kernel<<<1, 256>>>(fcw, fcb, out);
}